// round 4
// baseline (speedup 1.0000x reference)
#include <cuda_runtime.h>
#include <cuda_fp16.h>
#include <stdint.h>

// Problem dims
#define BATCH   512
#define INDIM   4096
#define OUTDIM  11008
#define NELEM   (OUTDIM * INDIM)        // 45,088,768

// ---------------- GEMM tiling ----------------
#define BM      128
#define BN      64
#define BK      64                      // 64 halves = 128B row -> SW128 atom
#define KTILES  (INDIM / BK)            // 64
#define STAGES  3
#define GTHREADS 128                    // 4 warps: 2 (m) x 2 (n), warp tile 64x32

#define XTILE_B (BM * BK * 2)           // 16384
#define WTILE_B (BN * BK * 2)           // 8192
#define STAGE_B (XTILE_B + WTILE_B)     // 24576
#define SMEM_B  (STAGES * STAGE_B)      // 73728

#define SW128(o) ((o) ^ (((o) >> 3) & 0x70))

// Device scratch (static; no runtime allocation)
__device__ __half    g_xh[BATCH * INDIM];   // x in fp16 (4 MB)
__device__ uint8_t   g_wc[NELEM];           // u8 magnitude codes (45 MB)
__device__ uint32_t  g_sg[NELEM / 32];      // bit-packed signs (5.6 MB)

// ---------------- PTX helpers (base PTX only) ----------------
__device__ __forceinline__ uint32_t smem_u32(const void* p) {
    return (uint32_t)__cvta_generic_to_shared(p);
}
__device__ __forceinline__ void cp16(uint32_t dst, const void* src) {
    asm volatile("cp.async.cg.shared.global [%0], [%1], 16;" :: "r"(dst), "l"(src));
}
__device__ __forceinline__ void cp_commit() {
    asm volatile("cp.async.commit_group;" ::: "memory");
}
__device__ __forceinline__ void cp_wait1() {
    asm volatile("cp.async.wait_group 1;" ::: "memory");
}
__device__ __forceinline__ void ldsm4(uint32_t* r, uint32_t addr) {
    asm volatile("ldmatrix.sync.aligned.m8n8.x4.shared.b16 {%0,%1,%2,%3}, [%4];"
                 : "=r"(r[0]), "=r"(r[1]), "=r"(r[2]), "=r"(r[3]) : "r"(addr));
}
__device__ __forceinline__ void mma16816(float* c, const uint32_t* a,
                                         uint32_t b0, uint32_t b1) {
    asm volatile(
        "mma.sync.aligned.m16n8k16.row.col.f32.f16.f16.f32 "
        "{%0,%1,%2,%3}, {%4,%5,%6,%7}, {%8,%9}, {%0,%1,%2,%3};"
        : "+f"(c[0]), "+f"(c[1]), "+f"(c[2]), "+f"(c[3])
        : "r"(a[0]), "r"(a[1]), "r"(a[2]), "r"(a[3]), "r"(b0), "r"(b1));
}
__device__ __forceinline__ float ex2(float v) {
    float r;
    asm("ex2.approx.f32 %0, %1;" : "=f"(r) : "f"(v));
    return r;
}

// ---------------- pass 1: x->fp16  +  QINS encode (u8 codes + sign bits) ----------------
#define XBLKS 2048                          // BATCH*INDIM / (256*4)
#define EBLKS (NELEM / 32 / 256)            // 5504

__global__ void prep_kernel(const float* __restrict__ x,
                            const int* __restrict__ stored,
                            const int* __restrict__ sign) {
    const int b = blockIdx.x;
    if (b < XBLKS) {
        // x fp32 -> fp16, one float4 per thread
        int i = b * 256 + threadIdx.x;
        float4 v = reinterpret_cast<const float4*>(x)[i];
        __half2* d = reinterpret_cast<__half2*>(g_xh);
        d[2 * i]     = __floats2half2_rn(v.x, v.y);
        d[2 * i + 1] = __floats2half2_rn(v.z, v.w);
    } else {
        // encode 32 consecutive weights per thread
        const size_t t  = (size_t)(b - XBLKS) * 256 + threadIdx.x;
        const size_t e0 = t * 32;
        uint32_t cw[8];
        uint32_t sg = 0;
#pragma unroll
        for (int wi = 0; wi < 8; wi++) {
            int4 s = __ldcs(reinterpret_cast<const int4*>(stored + e0) + wi);
            int4 g = __ldcs(reinterpret_cast<const int4*>(sign   + e0) + wi);
            cw[wi] = (uint32_t)s.x | ((uint32_t)s.y << 8)
                   | ((uint32_t)s.z << 16) | ((uint32_t)s.w << 24);
            sg |= ((uint32_t)((uint32_t)g.x >> 31)) << (4 * wi + 0);
            sg |= ((uint32_t)((uint32_t)g.y >> 31)) << (4 * wi + 1);
            sg |= ((uint32_t)((uint32_t)g.z >> 31)) << (4 * wi + 2);
            sg |= ((uint32_t)((uint32_t)g.w >> 31)) << (4 * wi + 3);
        }
        uint4* dst = reinterpret_cast<uint4*>(g_wc + e0);
        dst[0] = make_uint4(cw[0], cw[1], cw[2], cw[3]);
        dst[1] = make_uint4(cw[4], cw[5], cw[6], cw[7]);
        g_sg[t] = sg;
    }
}

// ---------------- pass 2: fused dequant + fp16 GEMM + epilogue ----------------
// out[m][n] = (sum_k x[m][k] * w[n][k] + bias[n]) * scale[n]
// w = sign * 2^(fA + fB * code)  reconstructed in the producer from u8 codes.
// Grid: (4 m-tiles fastest, 172 n-tiles) -> 4 CTAs share each W stripe via L2.
__global__ void __launch_bounds__(GTHREADS, 3) gemm_kernel(
    const float* __restrict__ log_min,
    const float* __restrict__ log_max,
    const float* __restrict__ scale,
    const float* __restrict__ bias,
    float* __restrict__ out) {
    extern __shared__ char smem[];
    const uint32_t sbase = smem_u32(smem);
    const int tid  = threadIdx.x;
    const int lane = tid & 31;
    const int w    = tid >> 5;
    const int wm   = w >> 1;          // 0..1 (64 m-rows each)
    const int wn   = w & 1;           // 0..1 (32 n-cols each)
    const int m0   = blockIdx.x * BM;
    const int n0   = blockIdx.y * BN;

    const float lmn = *log_min;
    const float dlt = *log_max - lmn;
    const float L2E = 1.44269504088896340736f;
    const float fB  = -dlt * (1.0f / 254.0f) * L2E;
    const float fA  = (lmn + dlt * (255.0f / 254.0f)) * L2E;

    float acc[4][4][4];
#pragma unroll
    for (int a = 0; a < 4; a++)
#pragma unroll
        for (int b = 0; b < 4; b++)
#pragma unroll
            for (int c = 0; c < 4; c++) acc[a][b][c] = 0.0f;

    // ---- x loader: 8 x cp16 per thread, SW128-swizzled ----
    const int chunk = tid & 7;        // 16B chunk within 128B row
    const int rbase = tid >> 3;       // 0..15
    auto issue_x = [&](int kt, int buf) {
        const int k0 = kt * BK;
        const uint32_t xb = sbase + (uint32_t)buf * STAGE_B;
#pragma unroll
        for (int i = 0; i < 8; i++) {
            const int row = rbase + 16 * i;
            const uint32_t off = SW128((uint32_t)(row * 128 + chunk * 16));
            cp16(xb + off, &g_xh[(size_t)(m0 + row) * INDIM + kt * BK + chunk * 8]);
        }
        (void)k0;
    };

    // ---- W producer: thread t -> row t>>1 (0..63), 32-col half t&1 ----
    const int wrow  = tid >> 1;
    const int wcol0 = (tid & 1) * 32;
    uint32_t wcw[8];         // 32 u8 codes
    uint32_t wsg;            // 32 sign bits
    auto load_w = [&](int kt) {
        const size_t gi = (size_t)(n0 + wrow) * INDIM + kt * BK + wcol0;
        uint4 c0 = *reinterpret_cast<const uint4*>(g_wc + gi);
        uint4 c1 = *reinterpret_cast<const uint4*>(g_wc + gi + 16);
        wcw[0] = c0.x; wcw[1] = c0.y; wcw[2] = c0.z; wcw[3] = c0.w;
        wcw[4] = c1.x; wcw[5] = c1.y; wcw[6] = c1.z; wcw[7] = c1.w;
        wsg = g_sg[gi >> 5];
    };
    auto store_w = [&](int buf) {
        const uint32_t wb = sbase + (uint32_t)buf * STAGE_B + XTILE_B;
        uint32_t packed[16];
#pragma unroll
        for (int wi = 0; wi < 8; wi++) {
            const uint32_t cwv = wcw[wi];
            uint32_t p0 = 0, p1 = 0;
            {
                float f0 = ex2(fA + fB * (float)(cwv & 0xFFu));
                float f1 = ex2(fA + fB * (float)((cwv >> 8) & 0xFFu));
                p0 = (uint32_t)__half_as_ushort(__float2half_rn(f0))
                   | ((uint32_t)__half_as_ushort(__float2half_rn(f1)) << 16);
                p0 ^= ((wsg >> (4 * wi)) & 1u) << 15;
                p0 ^= ((wsg >> (4 * wi + 1)) & 1u) << 31;
            }
            {
                float f2 = ex2(fA + fB * (float)((cwv >> 16) & 0xFFu));
                float f3 = ex2(fA + fB * (float)((cwv >> 24) & 0xFFu));
                p1 = (uint32_t)__half_as_ushort(__float2half_rn(f2))
                   | ((uint32_t)__half_as_ushort(__float2half_rn(f3)) << 16);
                p1 ^= ((wsg >> (4 * wi + 2)) & 1u) << 15;
                p1 ^= ((wsg >> (4 * wi + 3)) & 1u) << 31;
            }
            packed[2 * wi]     = p0;
            packed[2 * wi + 1] = p1;
        }
#pragma unroll
        for (int q = 0; q < 4; q++) {
            const uint32_t off = SW128((uint32_t)(wrow * 128 + wcol0 * 2 + q * 16));
            *reinterpret_cast<uint4*>(smem + (wb - sbase) + off) =
                make_uint4(packed[4 * q], packed[4 * q + 1],
                           packed[4 * q + 2], packed[4 * q + 3]);
        }
    };

    // ldmatrix lane address components
    const int a_row = lane & 15;
    const int a_kc  = (lane >> 4) << 3;
    const int b_row = (lane & 7) + (((lane >> 4) & 1) << 3);
    const int b_kc  = ((lane >> 3) & 1) << 3;

    // ---- prologue: x stages 0,1 async; W stages 0,1 synchronous ----
    issue_x(0, 0); cp_commit();
    issue_x(1, 1); cp_commit();
    load_w(0); store_w(0);
    load_w(1); store_w(1);

    for (int kt = 0; kt < KTILES; kt++) {
        const int buf = kt % STAGES;
        const int nk  = kt + 2;
        const int nbf = nk % STAGES;

        cp_wait1();
        __syncthreads();

        if (nk < KTILES) issue_x(nk, nbf);
        cp_commit();
        if (nk < KTILES) load_w(nk);     // LDG issued early; consumed after compute

        const uint32_t xb = sbase + (uint32_t)buf * STAGE_B;
        const uint32_t wb = xb + XTILE_B;
#pragma unroll
        for (int ks = 0; ks < 4; ks++) {
            uint32_t afr[4][4], bfr[2][4];
#pragma unroll
            for (int mi = 0; mi < 4; mi++) {
                const int row = wm * 64 + mi * 16 + a_row;
                ldsm4(afr[mi], xb + SW128((uint32_t)(row * 128 + (ks * 16 + a_kc) * 2)));
            }
#pragma unroll
            for (int bj = 0; bj < 2; bj++) {
                const int row = wn * 32 + bj * 16 + b_row;
                ldsm4(bfr[bj], wb + SW128((uint32_t)(row * 128 + (ks * 16 + b_kc) * 2)));
            }
#pragma unroll
            for (int mi = 0; mi < 4; mi++)
#pragma unroll
                for (int nj = 0; nj < 4; nj++)
                    mma16816(acc[mi][nj], afr[mi],
                             bfr[nj >> 1][(nj & 1) * 2],
                             bfr[nj >> 1][(nj & 1) * 2 + 1]);
        }

        if (nk < KTILES) store_w(nbf);   // after compute; barrier-protected for readers
    }

    // ---- epilogue: (acc + bias) * scale ----
    const int cbase = n0 + wn * 32 + (lane & 3) * 2;
#pragma unroll
    for (int nj = 0; nj < 4; nj++) {
        const int c = cbase + nj * 8;
        const float2 bb = *reinterpret_cast<const float2*>(&bias[c]);
        const float2 ss = *reinterpret_cast<const float2*>(&scale[c]);
#pragma unroll
        for (int mi = 0; mi < 4; mi++) {
            const int r0 = m0 + wm * 64 + mi * 16 + (lane >> 2);
            float2 o0, o1;
            o0.x = (acc[mi][nj][0] + bb.x) * ss.x;
            o0.y = (acc[mi][nj][1] + bb.y) * ss.y;
            o1.x = (acc[mi][nj][2] + bb.x) * ss.x;
            o1.y = (acc[mi][nj][3] + bb.y) * ss.y;
            *reinterpret_cast<float2*>(&out[(size_t)r0 * OUTDIM + c])       = o0;
            *reinterpret_cast<float2*>(&out[(size_t)(r0 + 8) * OUTDIM + c]) = o1;
        }
    }
}

// ---------------- harness entry ----------------
extern "C" void kernel_launch(void* const* d_in, const int* in_sizes, int n_in,
                              void* d_out, int out_size) {
    const float* x       = (const float*)d_in[0];
    const int*   stored  = (const int*)  d_in[1];
    const int*   sign    = (const int*)  d_in[2];
    const float* log_min = (const float*)d_in[3];
    const float* log_max = (const float*)d_in[4];
    const float* scale   = (const float*)d_in[5];
    const float* bias    = (const float*)d_in[6];
    float*       out     = (float*)d_out;
    (void)in_sizes; (void)n_in; (void)out_size;

    cudaFuncSetAttribute(gemm_kernel,
                         cudaFuncAttributeMaxDynamicSharedMemorySize, SMEM_B);

    // pass 1: x->fp16 + weight encode (u8 codes + sign bits)
    prep_kernel<<<XBLKS + EBLKS, 256>>>(x, stored, sign);

    // pass 2: fused dequant + GEMM + epilogue. m-tiles fastest for L2 W-sharing.
    dim3 grid(BATCH / BM, OUTDIM / BN);
    gemm_kernel<<<grid, GTHREADS, SMEM_B>>>(log_min, log_max, scale, bias, out);
}

// round 5
// speedup vs baseline: 1.5913x; 1.5913x over previous
#include <cuda_runtime.h>
#include <cuda_fp16.h>
#include <stdint.h>

// Problem dims
#define BATCH   512
#define INDIM   4096
#define OUTDIM  11008
#define NELEM   (OUTDIM * INDIM)        // 45,088,768

// ---------------- GEMM tiling ----------------
#define BM      128
#define BN      64
#define BK      64                      // 64 halves = 128B row -> SW128 atom
#define KTILES  (INDIM / BK)            // 64
#define STAGES  3
#define GTHREADS 128                    // 4 warps: 2 (m) x 2 (n), warp tile 64x32

#define XTILE_B (BM * BK * 2)           // 16384
#define WTILE_B (BN * BK * 2)           // 8192
#define STAGE_B (XTILE_B + WTILE_B)     // 24576
#define SMEM_B  (STAGES * STAGE_B)      // 73728 -> 3 CTAs/SM (216KB < 228KB)

#define SW128(o) ((o) ^ (((o) >> 3) & 0x70))

// Device scratch (static; no runtime allocation)
__device__ __half g_xh[BATCH * INDIM];   // x in fp16 (4 MB)
__device__ __half g_wh[NELEM];           // dequantized W in fp16 (90 MB)

// ---------------- PTX helpers (base PTX only) ----------------
__device__ __forceinline__ uint32_t smem_u32(const void* p) {
    return (uint32_t)__cvta_generic_to_shared(p);
}
__device__ __forceinline__ void cp16(uint32_t dst, const void* src) {
    asm volatile("cp.async.cg.shared.global [%0], [%1], 16;" :: "r"(dst), "l"(src));
}
__device__ __forceinline__ void cp_commit() {
    asm volatile("cp.async.commit_group;" ::: "memory");
}
__device__ __forceinline__ void cp_wait1() {
    asm volatile("cp.async.wait_group 1;" ::: "memory");
}
__device__ __forceinline__ void ldsm4(uint32_t* r, uint32_t addr) {
    asm volatile("ldmatrix.sync.aligned.m8n8.x4.shared.b16 {%0,%1,%2,%3}, [%4];"
                 : "=r"(r[0]), "=r"(r[1]), "=r"(r[2]), "=r"(r[3]) : "r"(addr));
}
__device__ __forceinline__ void mma16816(float* c, const uint32_t* a,
                                         uint32_t b0, uint32_t b1) {
    asm volatile(
        "mma.sync.aligned.m16n8k16.row.col.f32.f16.f16.f32 "
        "{%0,%1,%2,%3}, {%4,%5,%6,%7}, {%8,%9}, {%0,%1,%2,%3};"
        : "+f"(c[0]), "+f"(c[1]), "+f"(c[2]), "+f"(c[3])
        : "r"(a[0]), "r"(a[1]), "r"(a[2]), "r"(a[3]), "r"(b0), "r"(b1));
}
__device__ __forceinline__ float ex2(float v) {
    float r;
    asm("ex2.approx.f32 %0, %1;" : "=f"(r) : "f"(v));
    return r;
}

// ---------------- pass 1: x->fp16  +  QINS dequant -> fp16 weights ----------------
// w = sign * 2^(fA + fB * stored), fA/fB folded from log_min/log_max.
#define XBLKS  2048                     // BATCH*INDIM / (256*4)
#define DQBLKS (NELEM / (256 * 8))      // 22016

__global__ void prep_kernel(const float* __restrict__ x,
                            const int* __restrict__ stored,
                            const int* __restrict__ sign,
                            const float* __restrict__ log_min,
                            const float* __restrict__ log_max) {
    const int b = blockIdx.x;
    if (b < XBLKS) {
        // x fp32 -> fp16, one float4 per thread
        int i = b * 256 + threadIdx.x;
        float4 v = reinterpret_cast<const float4*>(x)[i];
        __half2* d = reinterpret_cast<__half2*>(g_xh);
        d[2 * i]     = __floats2half2_rn(v.x, v.y);
        d[2 * i + 1] = __floats2half2_rn(v.z, v.w);
    } else {
        // dequant 8 weights per thread, 16B store
        const size_t t  = (size_t)(b - XBLKS) * 256 + threadIdx.x;
        const size_t e0 = t * 8;
        const float lmn = *log_min;
        const float dlt = *log_max - lmn;
        const float L2E = 1.44269504088896340736f;
        const float fB  = -dlt * (1.0f / 254.0f) * L2E;
        const float fA  = (lmn + dlt * (255.0f / 254.0f)) * L2E;

        int4 s0 = __ldcs(reinterpret_cast<const int4*>(stored + e0));
        int4 s1 = __ldcs(reinterpret_cast<const int4*>(stored + e0) + 1);
        int4 g0 = __ldcs(reinterpret_cast<const int4*>(sign + e0));
        int4 g1 = __ldcs(reinterpret_cast<const int4*>(sign + e0) + 1);

        uint32_t h[8];
        h[0] = (uint32_t)__half_as_ushort(__float2half_rn(ex2(fA + fB * (float)s0.x)))
             ^ (((uint32_t)g0.x >> 16) & 0x8000u);
        h[1] = (uint32_t)__half_as_ushort(__float2half_rn(ex2(fA + fB * (float)s0.y)))
             ^ (((uint32_t)g0.y >> 16) & 0x8000u);
        h[2] = (uint32_t)__half_as_ushort(__float2half_rn(ex2(fA + fB * (float)s0.z)))
             ^ (((uint32_t)g0.z >> 16) & 0x8000u);
        h[3] = (uint32_t)__half_as_ushort(__float2half_rn(ex2(fA + fB * (float)s0.w)))
             ^ (((uint32_t)g0.w >> 16) & 0x8000u);
        h[4] = (uint32_t)__half_as_ushort(__float2half_rn(ex2(fA + fB * (float)s1.x)))
             ^ (((uint32_t)g1.x >> 16) & 0x8000u);
        h[5] = (uint32_t)__half_as_ushort(__float2half_rn(ex2(fA + fB * (float)s1.y)))
             ^ (((uint32_t)g1.y >> 16) & 0x8000u);
        h[6] = (uint32_t)__half_as_ushort(__float2half_rn(ex2(fA + fB * (float)s1.z)))
             ^ (((uint32_t)g1.z >> 16) & 0x8000u);
        h[7] = (uint32_t)__half_as_ushort(__float2half_rn(ex2(fA + fB * (float)s1.w)))
             ^ (((uint32_t)g1.w >> 16) & 0x8000u);

        uint4 p;
        p.x = h[0] | (h[1] << 16);
        p.y = h[2] | (h[3] << 16);
        p.z = h[4] | (h[5] << 16);
        p.w = h[6] | (h[7] << 16);
        *reinterpret_cast<uint4*>(g_wh + e0) = p;
    }
}

// ---------------- pass 2: fp16 GEMM (mma.sync) + epilogue ----------------
// out[m][n] = (sum_k x[m][k] * w[n][k] + bias[n]) * scale[n]
// Grid: (4 m-tiles fastest, 172 n-tiles) -> 4 CTAs share each W stripe via L2.
__global__ void __launch_bounds__(GTHREADS, 3) gemm_kernel(
    const float* __restrict__ scale,
    const float* __restrict__ bias,
    float* __restrict__ out) {
    extern __shared__ char smem[];
    const uint32_t sbase = smem_u32(smem);
    const int tid  = threadIdx.x;
    const int lane = tid & 31;
    const int w    = tid >> 5;
    const int wm   = w >> 1;          // 0..1 (64 m-rows each)
    const int wn   = w & 1;           // 0..1 (32 n-cols each)
    const int m0   = blockIdx.x * BM;
    const int n0   = blockIdx.y * BN;

    float acc[4][4][4];
#pragma unroll
    for (int a = 0; a < 4; a++)
#pragma unroll
        for (int b = 0; b < 4; b++)
#pragma unroll
            for (int c = 0; c < 4; c++) acc[a][b][c] = 0.0f;

    // ---- stage loader: X 8 x cp16, W 4 x cp16 per thread, SW128-swizzled ----
    const int chunk = tid & 7;        // 16B chunk within 128B row
    const int rbase = tid >> 3;       // 0..15
    auto load_stage = [&](int kt, int buf) {
        const int k0 = kt * BK;
        const uint32_t xb = sbase + (uint32_t)buf * STAGE_B;
        const uint32_t wb = xb + XTILE_B;
#pragma unroll
        for (int i = 0; i < 8; i++) {
            const int row = rbase + 16 * i;
            const uint32_t off = SW128((uint32_t)(row * 128 + chunk * 16));
            cp16(xb + off, &g_xh[(size_t)(m0 + row) * INDIM + k0 + chunk * 8]);
        }
#pragma unroll
        for (int i = 0; i < 4; i++) {
            const int row = rbase + 16 * i;
            const uint32_t off = SW128((uint32_t)(row * 128 + chunk * 16));
            cp16(wb + off, &g_wh[(size_t)(n0 + row) * INDIM + k0 + chunk * 8]);
        }
    };

    // ldmatrix lane address components
    const int a_row = lane & 15;
    const int a_kc  = (lane >> 4) << 3;
    const int b_row = (lane & 7) + (((lane >> 4) & 1) << 3);
    const int b_kc  = ((lane >> 3) & 1) << 3;

    // ---- prologue: fill 2 stages ----
    load_stage(0, 0); cp_commit();
    load_stage(1, 1); cp_commit();

    for (int kt = 0; kt < KTILES; kt++) {
        const int buf = kt % STAGES;
        const int nk  = kt + 2;

        cp_wait1();
        __syncthreads();

        if (nk < KTILES) load_stage(nk, nk % STAGES);
        cp_commit();   // uniform group counts (possibly empty)

        const uint32_t xb = sbase + (uint32_t)buf * STAGE_B;
        const uint32_t wb = xb + XTILE_B;
#pragma unroll
        for (int ks = 0; ks < 4; ks++) {
            uint32_t afr[4][4], bfr[2][4];
#pragma unroll
            for (int mi = 0; mi < 4; mi++) {
                const int row = wm * 64 + mi * 16 + a_row;
                ldsm4(afr[mi], xb + SW128((uint32_t)(row * 128 + (ks * 16 + a_kc) * 2)));
            }
#pragma unroll
            for (int bj = 0; bj < 2; bj++) {
                const int row = wn * 32 + bj * 16 + b_row;
                ldsm4(bfr[bj], wb + SW128((uint32_t)(row * 128 + (ks * 16 + b_kc) * 2)));
            }
#pragma unroll
            for (int mi = 0; mi < 4; mi++)
#pragma unroll
                for (int nj = 0; nj < 4; nj++)
                    mma16816(acc[mi][nj], afr[mi],
                             bfr[nj >> 1][(nj & 1) * 2],
                             bfr[nj >> 1][(nj & 1) * 2 + 1]);
        }
    }

    // ---- epilogue: (acc + bias) * scale ----
    const int cbase = n0 + wn * 32 + (lane & 3) * 2;
#pragma unroll
    for (int nj = 0; nj < 4; nj++) {
        const int c = cbase + nj * 8;
        const float2 bb = *reinterpret_cast<const float2*>(&bias[c]);
        const float2 ss = *reinterpret_cast<const float2*>(&scale[c]);
#pragma unroll
        for (int mi = 0; mi < 4; mi++) {
            const int r0 = m0 + wm * 64 + mi * 16 + (lane >> 2);
            float2 o0, o1;
            o0.x = (acc[mi][nj][0] + bb.x) * ss.x;
            o0.y = (acc[mi][nj][1] + bb.y) * ss.y;
            o1.x = (acc[mi][nj][2] + bb.x) * ss.x;
            o1.y = (acc[mi][nj][3] + bb.y) * ss.y;
            *reinterpret_cast<float2*>(&out[(size_t)r0 * OUTDIM + c])       = o0;
            *reinterpret_cast<float2*>(&out[(size_t)(r0 + 8) * OUTDIM + c]) = o1;
        }
    }
}

// ---------------- harness entry ----------------
extern "C" void kernel_launch(void* const* d_in, const int* in_sizes, int n_in,
                              void* d_out, int out_size) {
    const float* x       = (const float*)d_in[0];
    const int*   stored  = (const int*)  d_in[1];
    const int*   sign    = (const int*)  d_in[2];
    const float* log_min = (const float*)d_in[3];
    const float* log_max = (const float*)d_in[4];
    const float* scale   = (const float*)d_in[5];
    const float* bias    = (const float*)d_in[6];
    float*       out     = (float*)d_out;
    (void)in_sizes; (void)n_in; (void)out_size;

    cudaFuncSetAttribute(gemm_kernel,
                         cudaFuncAttributeMaxDynamicSharedMemorySize, SMEM_B);

    // pass 1: x->fp16 + weight dequant->fp16 scratch
    prep_kernel<<<XBLKS + DQBLKS, 256>>>(x, stored, sign, log_min, log_max);

    // pass 2: clean cp.async + HMMA GEMM. m-tiles fastest for L2 W-sharing.
    dim3 grid(BATCH / BM, OUTDIM / BN);
    gemm_kernel<<<grid, GTHREADS, SMEM_B>>>(scale, bias, out);
}